// round 4
// baseline (speedup 1.0000x reference)
#include <cuda_runtime.h>
#include <math.h>

#define NPTS 1024
#define DIM  64
#define HID  256
#define K    16
#define QB   8            // queries per block
#define RB   (QB * K)     // 128 pair rows per block
#define GRID 128
#define NT   1024

typedef unsigned long long ull;

__device__ float g_k[NPTS * DIM];
__device__ float g_v[NPTS * DIM];
__device__ unsigned g_bar;   // zero-initialized; advances by GRID per launch

// ---------------- packed fp32x2 helpers ----------------
__device__ __forceinline__ ull fma2(ull a, ull b, ull c) {
    ull d; asm("fma.rn.f32x2 %0, %1, %2, %3;" : "=l"(d) : "l"(a), "l"(b), "l"(c));
    return d;
}
__device__ __forceinline__ ull dup2(float x) {
    ull d; asm("mov.b64 %0, {%1, %1};" : "=l"(d) : "f"(x)); return d;
}
__device__ __forceinline__ ull pack2(float x, float y) {
    ull d; asm("mov.b64 %0, {%1, %2};" : "=l"(d) : "f"(x), "f"(y)); return d;
}
__device__ __forceinline__ float2 up2(ull v) {
    float2 r; asm("mov.b64 {%0, %1}, %2;" : "=f"(r.x), "=f"(r.y) : "l"(v)); return r;
}

// ---------------------------------------------------------------------------
// Fused kernel. grid 128, block 1024, 192KB dynamic smem.
// Dynamic smem (floats):
//   [0      , 8192 )  T (later aliased as SIM)
//   [8192   , 16384)  VG
//   [16384  , 32768)  Hh (128x128); E aliases [16384,24576); P2i aliases [24576,28672)
//   [32768  , 49152)  A2i ; ps (3072 floats) aliases [32768,35840) early
// ---------------------------------------------------------------------------
#define SMEM_FLOATS 49152

__global__ __launch_bounds__(NT)
void fused_kernel(const float* __restrict__ x,
                  const float* __restrict__ pos,
                  const float* __restrict__ Wq,
                  const float* __restrict__ Wk,
                  const float* __restrict__ Wv,
                  const float* __restrict__ P1, const float* __restrict__ pb1,
                  const float* __restrict__ P2, const float* __restrict__ pb2,
                  const float* __restrict__ A1, const float* __restrict__ ab1,
                  const float* __restrict__ A2, const float* __restrict__ ab2,
                  float* __restrict__ out) {
    extern __shared__ float sm[];
    float* T   = sm;
    float* VG  = sm + 8192;
    float* Hh  = sm + 16384;
    float* E   = Hh;
    float* P2i = Hh + 8192;
    float* A2i = sm + 32768;
    float* ps  = sm + 32768;         // aliases A2i during prolog

    __shared__ int   nb[RB];
    __shared__ float rp[RB][3];
    __shared__ float qrow[QB * DIM];
    __shared__ float xs[QB * DIM];
    __shared__ float cval[QB][4][K];
    __shared__ int   cidx[QB][4][K];
    __shared__ unsigned s_ticket;

    int tid = threadIdx.x;
    int ib = blockIdx.x * QB;
    int w = tid >> 5, lane = tid & 31;

    // ---- Step 0: stage pos, x rows, P2 interleaved ----
    for (int t = tid; t < NPTS * 3; t += NT) ps[t] = pos[t];
    if (tid < QB * DIM) xs[tid] = x[ib * DIM + tid];
    for (int t = tid; t < 4096; t += NT) {
        int s = t & 1, d = (t >> 1) & 63, h2 = t >> 7;
        P2i[t] = P2[(2 * h2 + s) * DIM + d];
    }
    __syncthreads();

    // ---- Step 1: qkv for this block's 8 rows (1536 outputs over 1024 threads) ----
    for (int t = tid; t < 3 * QB * DIM; t += NT) {
        int kind = t >> 9;          // 0=q 1=k 2=v
        int rd = t & 511;
        int r = rd >> 6, d = rd & 63;
        const float* W = (kind == 0) ? Wq : (kind == 1) ? Wk : Wv;
        float acc = 0.f;
#pragma unroll 8
        for (int c = 0; c < DIM; c++) acc += xs[r * DIM + c] * W[c * DIM + d];
        if (kind == 0)      qrow[rd] = acc;
        else if (kind == 1) g_k[(ib + r) * DIM + d] = acc;
        else                g_v[(ib + r) * DIM + d] = acc;
    }
    __syncthreads();
    if (tid == 0) {
        __threadfence();
        s_ticket = atomicAdd(&g_bar, 1u);
    }

    // ---- Step 2: kNN, 4 warps per query, 256 candidates per warp ----
    {
        int qq = w >> 2, part = w & 3;
        int gi = ib + qq;
        float px = ps[gi * 3 + 0], py = ps[gi * 3 + 1], pz = ps[gi * 3 + 2];
        float v[8]; int id[8];
#pragma unroll
        for (int c = 0; c < 8; c++) {
            int j = part * 256 + c * 32 + lane;
            float dx = px - ps[j * 3 + 0];
            float dy = py - ps[j * 3 + 1];
            float dz = pz - ps[j * 3 + 2];
            v[c] = dx * dx + dy * dy + dz * dz;
            id[c] = j;
        }
        for (int r = 0; r < K; r++) {
            float bv = v[0]; int bi = id[0];
#pragma unroll
            for (int c = 1; c < 8; c++)
                if (v[c] < bv || (v[c] == bv && id[c] < bi)) { bv = v[c]; bi = id[c]; }
#pragma unroll
            for (int off = 16; off > 0; off >>= 1) {
                float ov = __shfl_down_sync(0xffffffffu, bv, off);
                int   oi = __shfl_down_sync(0xffffffffu, bi, off);
                if (ov < bv || (ov == bv && oi < bi)) { bv = ov; bi = oi; }
            }
            bv = __shfl_sync(0xffffffffu, bv, 0);
            bi = __shfl_sync(0xffffffffu, bi, 0);
            if (lane == 0) { cval[qq][part][r] = bv; cidx[qq][part][r] = bi; }
#pragma unroll
            for (int c = 0; c < 8; c++) if (id[c] == bi) v[c] = 3.4e38f;
        }
    }
    __syncthreads();
    // merge 64 candidates per query on warps with (w&3)==0 (2 cands per lane)
    if ((w & 3) == 0) {
        int qq = w >> 2;
        float mv[2]; int mi[2];
#pragma unroll
        for (int c = 0; c < 2; c++) {
            int ci = lane * 2 + c;
            mv[c] = cval[qq][ci >> 4][ci & 15];
            mi[c] = cidx[qq][ci >> 4][ci & 15];
        }
        for (int r = 0; r < K; r++) {
            float bv = mv[0]; int bi = mi[0];
            if (mv[1] < bv || (mv[1] == bv && mi[1] < bi)) { bv = mv[1]; bi = mi[1]; }
#pragma unroll
            for (int off = 16; off > 0; off >>= 1) {
                float ov = __shfl_down_sync(0xffffffffu, bv, off);
                int   oi = __shfl_down_sync(0xffffffffu, bi, off);
                if (ov < bv || (ov == bv && oi < bi)) { bv = ov; bi = oi; }
            }
            bi = __shfl_sync(0xffffffffu, bi, 0);
            if (lane == 0) nb[qq * K + r] = bi;
#pragma unroll
            for (int c = 0; c < 2; c++) if (mi[c] == bi) mv[c] = 3.4e38f;
        }
    }
    __syncthreads();

    // rel_pos from staged ps (before A2i overwrites it)
    if (tid < RB * 3) {
        int r = tid / 3, c = tid - r * 3;
        int gi = ib + (r >> 4);
        rp[r][c] = ps[gi * 3 + c] - ps[nb[r] * 3 + c];
    }
    __syncthreads();

    // ---- Step 3: stage A2 interleaved (overwrites ps); tid0 waits on barrier ----
    for (int t = tid; t < 16384; t += NT) {
        int s = t & 1, d = (t >> 1) & 63, e2 = t >> 7;
        A2i[t] = A2[(2 * e2 + s) * DIM + d];
    }
    if (tid == 0) {
        unsigned target = (s_ticket / GRID + 1u) * GRID;
        while ((int)(*(volatile unsigned*)&g_bar - target) < 0) { }
        __threadfence();
    }
    __syncthreads();

    // ---- Phase 1a: E = relu(rp @ P1 + pb1) ----
    for (int t = tid; t < RB * 64; t += NT) {
        int r = t >> 6, h = t & 63;
        float e = rp[r][0] * P1[h] + rp[r][1] * P1[64 + h]
                + rp[r][2] * P1[128 + h] + pb1[h];
        E[t] = fmaxf(e, 0.f);
    }
    __syncthreads();

    int r0 = w * 4;                 // 4 rows per warp
    int d0 = lane, d1 = lane + 32;

    // ---- Phase 1b: rpe = E @ P2 + pb2 ; T = q - k + rpe ; VG = v + rpe ----
    {
        ull aA[4], aB[4];
#pragma unroll
        for (int u = 0; u < 4; u++) { aA[u] = 0ULL; aB[u] = 0ULL; }
#pragma unroll 4
        for (int h2 = 0; h2 < 32; h2 += 2) {
            ull p00 = *(const ull*)(P2i + (((h2 << 6) + d0) << 1));
            ull p01 = *(const ull*)(P2i + (((h2 << 6) + d1) << 1));
            ull p10 = *(const ull*)(P2i + ((((h2 + 1) << 6) + d0) << 1));
            ull p11 = *(const ull*)(P2i + ((((h2 + 1) << 6) + d1) << 1));
#pragma unroll
            for (int u = 0; u < 4; u++) {
                ulonglong2 ev = *(const ulonglong2*)(E + ((r0 + u) << 6) + (h2 << 1));
                aA[u] = fma2(ev.x, p00, aA[u]);
                aB[u] = fma2(ev.x, p01, aB[u]);
                aA[u] = fma2(ev.y, p10, aA[u]);
                aB[u] = fma2(ev.y, p11, aB[u]);
            }
        }
        float b0 = pb2[d0], b1 = pb2[d1];
#pragma unroll
        for (int u = 0; u < 4; u++) {
            int r = r0 + u;
            int j = nb[r];
            int qq = r >> 4;
            float2 fa = up2(aA[u]); float rpe0 = fa.x + fa.y + b0;
            float2 fb = up2(aB[u]); float rpe1 = fb.x + fb.y + b1;
            T[r * 64 + d0]  = qrow[qq * 64 + d0] - g_k[j * 64 + d0] + rpe0;
            VG[r * 64 + d0] = g_v[j * 64 + d0] + rpe0;
            T[r * 64 + d1]  = qrow[qq * 64 + d1] - g_k[j * 64 + d1] + rpe1;
            VG[r * 64 + d1] = g_v[j * 64 + d1] + rpe1;
        }
    }
    __syncthreads();

    // ---- Phases 2+3 over two e-halves; phase-3 accumulators persist ----
    ull sA[4], sB[4];
#pragma unroll
    for (int u = 0; u < 4; u++) { sA[u] = 0ULL; sB[u] = 0ULL; }
    int e0 = lane << 2;

    for (int half = 0; half < 2; half++) {
        // Phase 2: Hh = relu(T @ A1[:, half*128 +128) + ab1)
        {
            const float* A1h = A1 + half * 128 + e0;
            float4 b = *(const float4*)(ab1 + half * 128 + e0);
            ull acc0[4], acc1[4];
#pragma unroll
            for (int u = 0; u < 4; u++) {
                acc0[u] = pack2(b.x, b.y);
                acc1[u] = pack2(b.z, b.w);
            }
#pragma unroll 2
            for (int d4 = 0; d4 < 16; d4++) {
                float4 tv[4];
#pragma unroll
                for (int u = 0; u < 4; u++)
                    tv[u] = *(const float4*)(T + ((r0 + u) << 6) + (d4 << 2));
#pragma unroll
                for (int j = 0; j < 4; j++) {
                    ulonglong2 av = *(const ulonglong2*)(A1h + (d4 * 4 + j) * HID);
#pragma unroll
                    for (int u = 0; u < 4; u++) {
                        float tj = (j == 0) ? tv[u].x : (j == 1) ? tv[u].y
                                 : (j == 2) ? tv[u].z : tv[u].w;
                        ull tt = dup2(tj);
                        acc0[u] = fma2(tt, av.x, acc0[u]);
                        acc1[u] = fma2(tt, av.y, acc1[u]);
                    }
                }
            }
#pragma unroll
            for (int u = 0; u < 4; u++) {
                float2 h0 = up2(acc0[u]);
                float2 h1 = up2(acc1[u]);
                float4 hv = make_float4(fmaxf(h0.x, 0.f), fmaxf(h0.y, 0.f),
                                        fmaxf(h1.x, 0.f), fmaxf(h1.y, 0.f));
                *(float4*)(Hh + ((r0 + u) << 7) + e0) = hv;
            }
        }
        __syncthreads();

        // Phase 3 accumulate: SIM += Hh @ A2[half*128 +128, :]
#pragma unroll 2
        for (int e2l = 0; e2l < 64; e2l += 2) {
            int e2 = (half << 6) + e2l;
            ull a00 = *(const ull*)(A2i + (((e2 << 6) + d0) << 1));
            ull a01 = *(const ull*)(A2i + (((e2 << 6) + d1) << 1));
            ull a10 = *(const ull*)(A2i + ((((e2 + 1) << 6) + d0) << 1));
            ull a11 = *(const ull*)(A2i + ((((e2 + 1) << 6) + d1) << 1));
#pragma unroll
            for (int u = 0; u < 4; u++) {
                ulonglong2 hv = *(const ulonglong2*)(Hh + ((r0 + u) << 7) + (e2l << 1));
                sA[u] = fma2(hv.x, a00, sA[u]);
                sB[u] = fma2(hv.x, a01, sB[u]);
                sA[u] = fma2(hv.y, a10, sA[u]);
                sB[u] = fma2(hv.y, a11, sB[u]);
            }
        }
        __syncthreads();
    }

    // ---- Phase 3 epilogue: SIM (aliases T) ----
    {
        float b0 = ab2[d0], b1 = ab2[d1];
#pragma unroll
        for (int u = 0; u < 4; u++) {
            int r = r0 + u;
            float2 fa = up2(sA[u]);
            float2 fb = up2(sB[u]);
            T[r * 64 + d0] = fa.x + fa.y + b0;
            T[r * 64 + d1] = fb.x + fb.y + b1;
        }
    }
    __syncthreads();

    // ---- Phase 4: softmax over K neighbors + weighted sum of VG ----
    if (tid < 512) {
        int qq = tid >> 6, d = tid & 63;
        int base = qq * K;
        float m = -3.4e38f;
#pragma unroll
        for (int kk = 0; kk < K; kk++) m = fmaxf(m, T[(base + kk) * 64 + d]);
        float s = 0.f, agg = 0.f;
#pragma unroll
        for (int kk = 0; kk < K; kk++) {
            float wv = __expf(T[(base + kk) * 64 + d] - m);
            s += wv;
            agg += wv * VG[(base + kk) * 64 + d];
        }
        out[(ib + qq) * 64 + d] = agg / s;
    }
}

// ---------------------------------------------------------------------------
extern "C" void kernel_launch(void* const* d_in, const int* in_sizes, int n_in,
                              void* d_out, int out_size) {
    const float* x   = (const float*)d_in[0];
    const float* pos = (const float*)d_in[1];
    const float* Wq  = (const float*)d_in[2];
    const float* Wk  = (const float*)d_in[3];
    const float* Wv  = (const float*)d_in[4];
    const float* P1  = (const float*)d_in[5];
    const float* pb1 = (const float*)d_in[6];
    const float* P2  = (const float*)d_in[7];
    const float* pb2 = (const float*)d_in[8];
    const float* A1  = (const float*)d_in[9];
    const float* ab1 = (const float*)d_in[10];
    const float* A2  = (const float*)d_in[11];
    const float* ab2 = (const float*)d_in[12];
    float* out = (float*)d_out;

    cudaFuncSetAttribute(fused_kernel, cudaFuncAttributeMaxDynamicSharedMemorySize,
                         SMEM_FLOATS * sizeof(float));
    fused_kernel<<<GRID, NT, SMEM_FLOATS * sizeof(float)>>>(
        x, pos, Wq, Wk, Wv, P1, pb1, P2, pb2, A1, ab1, A2, ab2, out);
}

// round 5
// speedup vs baseline: 1.1707x; 1.1707x over previous
#include <cuda_runtime.h>
#include <math.h>

#define NPTS 1024
#define DIM  64
#define HID  256
#define K    16
#define QB   8            // queries per block
#define RB   (QB * K)     // 128 pair rows per block
#define GRID 128
#define NT   512

typedef unsigned long long ull;

__device__ float g_k[NPTS * DIM];
__device__ float g_v[NPTS * DIM];
__device__ unsigned g_bar;   // zero-initialized; advances by GRID per launch

// ---------------- packed fp32x2 helpers ----------------
__device__ __forceinline__ ull fma2(ull a, ull b, ull c) {
    ull d; asm("fma.rn.f32x2 %0, %1, %2, %3;" : "=l"(d) : "l"(a), "l"(b), "l"(c));
    return d;
}
__device__ __forceinline__ ull dup2(float x) {
    ull d; asm("mov.b64 %0, {%1, %1};" : "=l"(d) : "f"(x)); return d;
}
__device__ __forceinline__ ull pack2(float x, float y) {
    ull d; asm("mov.b64 %0, {%1, %2};" : "=l"(d) : "f"(x), "f"(y)); return d;
}
__device__ __forceinline__ float2 up2(ull v) {
    float2 r; asm("mov.b64 {%0, %1}, %2;" : "=f"(r.x), "=f"(r.y) : "l"(v)); return r;
}

// ---------------------------------------------------------------------------
// Fused kernel. grid 128, block 512, 192KB dynamic smem.
// Dynamic smem (floats):
//   [0      , 8192 )  T (later aliased as SIM)
//   [8192   , 16384)  VG
//   [16384  , 32768)  Hh (128x128); E aliases [16384,24576); P2i aliases [24576,28672)
//   [32768  , 49152)  A2i ; ps (3072 floats) aliases [32768,35840) early
// ---------------------------------------------------------------------------
#define SMEM_FLOATS 49152

__global__ __launch_bounds__(NT)
void fused_kernel(const float* __restrict__ x,
                  const float* __restrict__ pos,
                  const float* __restrict__ Wq,
                  const float* __restrict__ Wk,
                  const float* __restrict__ Wv,
                  const float* __restrict__ P1, const float* __restrict__ pb1,
                  const float* __restrict__ P2, const float* __restrict__ pb2,
                  const float* __restrict__ A1, const float* __restrict__ ab1,
                  const float* __restrict__ A2, const float* __restrict__ ab2,
                  float* __restrict__ out) {
    extern __shared__ float sm[];
    float* T   = sm;
    float* VG  = sm + 8192;
    float* Hh  = sm + 16384;
    float* E   = Hh;
    float* P2i = Hh + 8192;
    float* A2i = sm + 32768;
    float* ps  = sm + 32768;         // aliases A2i during prolog

    __shared__ int   nb[RB];
    __shared__ float rp[RB][3];
    __shared__ float qrow[QB * DIM];
    __shared__ float xs[QB * DIM];
    __shared__ float cval[QB][2][K];
    __shared__ int   cidx[QB][2][K];
    __shared__ unsigned s_ticket;

    int tid = threadIdx.x;
    int ib = blockIdx.x * QB;
    int w = tid >> 5, lane = tid & 31;

    // ---- Step 0: stage pos, x rows, P2 interleaved ----
    for (int t = tid; t < NPTS * 3; t += NT) ps[t] = pos[t];
    for (int t = tid; t < QB * DIM; t += NT) xs[t] = x[ib * DIM + t];
    for (int t = tid; t < 4096; t += NT) {
        int s = t & 1, d = (t >> 1) & 63, h2 = t >> 7;
        P2i[t] = P2[(2 * h2 + s) * DIM + d];
    }
    __syncthreads();

    // ---- Step 1: qkv for this block's 8 rows ----
    {
        int r = tid >> 6, d = tid & 63;
        float q = 0.f, kk = 0.f, vv = 0.f;
#pragma unroll 4
        for (int c = 0; c < DIM; c++) {
            float xv = xs[r * DIM + c];
            q  += xv * Wq[c * DIM + d];
            kk += xv * Wk[c * DIM + d];
            vv += xv * Wv[c * DIM + d];
        }
        qrow[r * DIM + d] = q;
        g_k[(ib + r) * DIM + d] = kk;
        g_v[(ib + r) * DIM + d] = vv;
    }
    __syncthreads();
    if (tid == 0) {
        __threadfence();
        s_ticket = atomicAdd(&g_bar, 1u);
    }

    // ---- Step 2: kNN for 8 queries (2 warps per query, 512 candidates each) ----
    {
        int qq = w >> 1, hh = w & 1;
        int gi = ib + qq;
        float px = ps[gi * 3 + 0], py = ps[gi * 3 + 1], pz = ps[gi * 3 + 2];
        float v[16]; int id[16];
#pragma unroll
        for (int c = 0; c < 16; c++) {
            int j = hh * 512 + c * 32 + lane;
            float dx = px - ps[j * 3 + 0];
            float dy = py - ps[j * 3 + 1];
            float dz = pz - ps[j * 3 + 2];
            v[c] = dx * dx + dy * dy + dz * dz;
            id[c] = j;
        }
        for (int r = 0; r < K; r++) {
            float bv = v[0]; int bi = id[0];
#pragma unroll
            for (int c = 1; c < 16; c++)
                if (v[c] < bv || (v[c] == bv && id[c] < bi)) { bv = v[c]; bi = id[c]; }
#pragma unroll
            for (int off = 16; off > 0; off >>= 1) {
                float ov = __shfl_down_sync(0xffffffffu, bv, off);
                int   oi = __shfl_down_sync(0xffffffffu, bi, off);
                if (ov < bv || (ov == bv && oi < bi)) { bv = ov; bi = oi; }
            }
            bv = __shfl_sync(0xffffffffu, bv, 0);
            bi = __shfl_sync(0xffffffffu, bi, 0);
            if (lane == 0) { cval[qq][hh][r] = bv; cidx[qq][hh][r] = bi; }
#pragma unroll
            for (int c = 0; c < 16; c++) if (id[c] == bi) v[c] = 3.4e38f;
        }
    }
    __syncthreads();
    // merge the two halves per query: even warps, 32 candidates on 32 lanes
    if ((w & 1) == 0) {
        int qq = w >> 1;
        float mv = cval[qq][lane >> 4][lane & 15];
        int   mi = cidx[qq][lane >> 4][lane & 15];
        for (int r = 0; r < K; r++) {
            float bv = mv; int bi = mi;
#pragma unroll
            for (int off = 16; off > 0; off >>= 1) {
                float ov = __shfl_down_sync(0xffffffffu, bv, off);
                int   oi = __shfl_down_sync(0xffffffffu, bi, off);
                if (ov < bv || (ov == bv && oi < bi)) { bv = ov; bi = oi; }
            }
            bi = __shfl_sync(0xffffffffu, bi, 0);
            if (lane == 0) nb[qq * K + r] = bi;
            if (mi == bi) mv = 3.4e38f;
        }
    }
    __syncthreads();

    // rel_pos from staged ps (before A2i overwrites it)
    for (int t = tid; t < RB * 3; t += NT) {
        int r = t / 3, c = t - r * 3;
        int gi = ib + (r >> 4);
        rp[r][c] = ps[gi * 3 + c] - ps[nb[r] * 3 + c];
    }
    __syncthreads();

    // ---- Step 3: stage A2 interleaved (overwrites ps); tid0 waits on barrier ----
    for (int t = tid; t < 16384; t += NT) {
        int s = t & 1, d = (t >> 1) & 63, e2 = t >> 7;
        A2i[t] = A2[(2 * e2 + s) * DIM + d];
    }
    if (tid == 0) {
        unsigned target = (s_ticket / GRID + 1u) * GRID;
        while ((int)(*(volatile unsigned*)&g_bar - target) < 0) { }
        __threadfence();
    }
    __syncthreads();

    // ---- Phase 1a: E = relu(rp @ P1 + pb1) ----
    for (int t = tid; t < RB * 64; t += NT) {
        int r = t >> 6, h = t & 63;
        float e = rp[r][0] * P1[h] + rp[r][1] * P1[64 + h]
                + rp[r][2] * P1[128 + h] + pb1[h];
        E[t] = fmaxf(e, 0.f);
    }
    __syncthreads();

    int r0 = w * 8;
    int d0 = lane, d1 = lane + 32;

    // ---- Phase 1b: rpe = E @ P2 + pb2 ; T = q - k + rpe ; VG = v + rpe ----
    {
        ull aA[8], aB[8];
#pragma unroll
        for (int u = 0; u < 8; u++) { aA[u] = 0ULL; aB[u] = 0ULL; }
#pragma unroll 4
        for (int h2 = 0; h2 < 32; h2 += 2) {
            ull p00 = *(const ull*)(P2i + (((h2 << 6) + d0) << 1));
            ull p01 = *(const ull*)(P2i + (((h2 << 6) + d1) << 1));
            ull p10 = *(const ull*)(P2i + ((((h2 + 1) << 6) + d0) << 1));
            ull p11 = *(const ull*)(P2i + ((((h2 + 1) << 6) + d1) << 1));
#pragma unroll
            for (int u = 0; u < 8; u++) {
                ulonglong2 ev = *(const ulonglong2*)(E + ((r0 + u) << 6) + (h2 << 1));
                aA[u] = fma2(ev.x, p00, aA[u]);
                aB[u] = fma2(ev.x, p01, aB[u]);
                aA[u] = fma2(ev.y, p10, aA[u]);
                aB[u] = fma2(ev.y, p11, aB[u]);
            }
        }
        float b0 = pb2[d0], b1 = pb2[d1];
#pragma unroll
        for (int u = 0; u < 8; u++) {
            int r = r0 + u;
            int j = nb[r];
            int qq = r >> 4;
            float2 fa = up2(aA[u]); float rpe0 = fa.x + fa.y + b0;
            float2 fb = up2(aB[u]); float rpe1 = fb.x + fb.y + b1;
            T[r * 64 + d0]  = qrow[qq * 64 + d0] - g_k[j * 64 + d0] + rpe0;
            VG[r * 64 + d0] = g_v[j * 64 + d0] + rpe0;
            T[r * 64 + d1]  = qrow[qq * 64 + d1] - g_k[j * 64 + d1] + rpe1;
            VG[r * 64 + d1] = g_v[j * 64 + d1] + rpe1;
        }
    }
    __syncthreads();

    // ---- Phases 2+3 over two e-halves; phase-3 accumulators persist ----
    ull sA[8], sB[8];
#pragma unroll
    for (int u = 0; u < 8; u++) { sA[u] = 0ULL; sB[u] = 0ULL; }
    int e0 = lane << 2;

    for (int half = 0; half < 2; half++) {
        // Phase 2: Hh = relu(T @ A1[:, half*128 +128) + ab1)
        {
            const float* A1h = A1 + half * 128 + e0;
            float4 b = *(const float4*)(ab1 + half * 128 + e0);
            ull acc0[8], acc1[8];
#pragma unroll
            for (int u = 0; u < 8; u++) {
                acc0[u] = pack2(b.x, b.y);
                acc1[u] = pack2(b.z, b.w);
            }
#pragma unroll 4
            for (int d2 = 0; d2 < 32; d2++) {
                ulonglong2 av0 = *(const ulonglong2*)(A1h + (2 * d2) * HID);
                ulonglong2 av1 = *(const ulonglong2*)(A1h + (2 * d2 + 1) * HID);
#pragma unroll
                for (int u = 0; u < 8; u++) {
                    float2 tp = *(const float2*)(T + ((r0 + u) << 6) + 2 * d2);
                    ull t0 = dup2(tp.x);
                    ull t1 = dup2(tp.y);
                    acc0[u] = fma2(t0, av0.x, acc0[u]);
                    acc1[u] = fma2(t0, av0.y, acc1[u]);
                    acc0[u] = fma2(t1, av1.x, acc0[u]);
                    acc1[u] = fma2(t1, av1.y, acc1[u]);
                }
            }
#pragma unroll
            for (int u = 0; u < 8; u++) {
                float2 h0 = up2(acc0[u]);
                float2 h1 = up2(acc1[u]);
                float4 hv = make_float4(fmaxf(h0.x, 0.f), fmaxf(h0.y, 0.f),
                                        fmaxf(h1.x, 0.f), fmaxf(h1.y, 0.f));
                *(float4*)(Hh + ((r0 + u) << 7) + e0) = hv;
            }
        }
        __syncthreads();

        // Phase 3 accumulate: SIM += Hh @ A2[half*128 +128, :]
#pragma unroll 2
        for (int e2l = 0; e2l < 64; e2l += 2) {
            int e2 = (half << 6) + e2l;
            ull a00 = *(const ull*)(A2i + (((e2 << 6) + d0) << 1));
            ull a01 = *(const ull*)(A2i + (((e2 << 6) + d1) << 1));
            ull a10 = *(const ull*)(A2i + ((((e2 + 1) << 6) + d0) << 1));
            ull a11 = *(const ull*)(A2i + ((((e2 + 1) << 6) + d1) << 1));
#pragma unroll
            for (int u = 0; u < 8; u++) {
                ulonglong2 hv = *(const ulonglong2*)(Hh + ((r0 + u) << 7) + (e2l << 1));
                sA[u] = fma2(hv.x, a00, sA[u]);
                sB[u] = fma2(hv.x, a01, sB[u]);
                sA[u] = fma2(hv.y, a10, sA[u]);
                sB[u] = fma2(hv.y, a11, sB[u]);
            }
        }
        __syncthreads();
    }

    // ---- Phase 3 epilogue: SIM (aliases T) ----
    {
        float b0 = ab2[d0], b1 = ab2[d1];
#pragma unroll
        for (int u = 0; u < 8; u++) {
            int r = r0 + u;
            float2 fa = up2(sA[u]);
            float2 fb = up2(sB[u]);
            T[r * 64 + d0] = fa.x + fa.y + b0;
            T[r * 64 + d1] = fb.x + fb.y + b1;
        }
    }
    __syncthreads();

    // ---- Phase 4: softmax over K neighbors + weighted sum of VG ----
    {
        int qq = tid >> 6, d = tid & 63;
        int base = qq * K;
        float m = -3.4e38f;
#pragma unroll
        for (int kk = 0; kk < K; kk++) m = fmaxf(m, T[(base + kk) * 64 + d]);
        float s = 0.f, agg = 0.f;
#pragma unroll
        for (int kk = 0; kk < K; kk++) {
            float wv = __expf(T[(base + kk) * 64 + d] - m);
            s += wv;
            agg += wv * VG[(base + kk) * 64 + d];
        }
        out[(ib + qq) * 64 + d] = agg / s;
    }
}

// ---------------------------------------------------------------------------
extern "C" void kernel_launch(void* const* d_in, const int* in_sizes, int n_in,
                              void* d_out, int out_size) {
    const float* x   = (const float*)d_in[0];
    const float* pos = (const float*)d_in[1];
    const float* Wq  = (const float*)d_in[2];
    const float* Wk  = (const float*)d_in[3];
    const float* Wv  = (const float*)d_in[4];
    const float* P1  = (const float*)d_in[5];
    const float* pb1 = (const float*)d_in[6];
    const float* P2  = (const float*)d_in[7];
    const float* pb2 = (const float*)d_in[8];
    const float* A1  = (const float*)d_in[9];
    const float* ab1 = (const float*)d_in[10];
    const float* A2  = (const float*)d_in[11];
    const float* ab2 = (const float*)d_in[12];
    float* out = (float*)d_out;

    cudaFuncSetAttribute(fused_kernel, cudaFuncAttributeMaxDynamicSharedMemorySize,
                         SMEM_FLOATS * sizeof(float));
    fused_kernel<<<GRID, NT, SMEM_FLOATS * sizeof(float)>>>(
        x, pos, Wq, Wk, Wv, P1, pb1, P2, pb2, A1, ab1, A2, ab2, out);
}